// round 3
// baseline (speedup 1.0000x reference)
#include <cuda_runtime.h>
#include <cuda_bf16.h>
#include <cstddef>

// Problem constants
#define B_ 2
#define L_ 2048
#define DM 1024
#define H_ 16
#define DH 64
#define MROWS (B_ * L_)   // 4096

// ---------------- scratch (no allocation allowed) ----------------
__device__ float g_qh[MROWS * DM];
__device__ float g_kh[MROWS * DM];
__device__ float g_vh[MROWS * DM];
__device__ float g_att[MROWS * DM];

// ---------------- SGEMM: C[M,N] = A[M,K] * B[K,N], fp32 ----------------
// BM=128, BN=128, BK=16, 256 threads, 8x8 microtile. M%128==0, N%128==0, K%16==0.
#define BM 128
#define BN 128
#define BK 16

__global__ __launch_bounds__(256) void sgemm_kernel(
    const float* __restrict__ A, const float* __restrict__ Bm,
    float* __restrict__ C, int M, int N, int K)
{
    __shared__ float As[BK][BM];
    __shared__ float Bs[BK][BN];

    int tid = threadIdx.x;
    int tx = tid & 15;       // 0..15  -> col group
    int ty = tid >> 4;       // 0..15  -> row group
    int rowBase = blockIdx.y * BM;
    int colBase = blockIdx.x * BN;

    float acc[8][8];
#pragma unroll
    for (int i = 0; i < 8; i++)
#pragma unroll
        for (int j = 0; j < 8; j++) acc[i][j] = 0.f;

    for (int k0 = 0; k0 < K; k0 += BK) {
#pragma unroll
        for (int it = 0; it < 2; it++) {
            int idx = tid + it * 256;           // 0..511
            // A tile: 128 rows x 16 cols = 512 float4 (4 per row)
            int ar = idx >> 2;
            int ac4 = idx & 3;
            float4 a = *(const float4*)(A + (size_t)(rowBase + ar) * K + k0 + ac4 * 4);
            As[ac4 * 4 + 0][ar] = a.x;
            As[ac4 * 4 + 1][ar] = a.y;
            As[ac4 * 4 + 2][ar] = a.z;
            As[ac4 * 4 + 3][ar] = a.w;
            // B tile: 16 rows x 128 cols = 512 float4 (32 per row)
            int br = idx >> 5;
            int bc4 = idx & 31;
            float4 b = *(const float4*)(Bm + (size_t)(k0 + br) * N + colBase + bc4 * 4);
            *(float4*)(&Bs[br][bc4 * 4]) = b;
        }
        __syncthreads();

#pragma unroll
        for (int kk = 0; kk < BK; kk++) {
            float ra[8], rb[8];
            float4 a0 = *(float4*)(&As[kk][ty * 8]);
            float4 a1 = *(float4*)(&As[kk][ty * 8 + 4]);
            ra[0]=a0.x; ra[1]=a0.y; ra[2]=a0.z; ra[3]=a0.w;
            ra[4]=a1.x; ra[5]=a1.y; ra[6]=a1.z; ra[7]=a1.w;
            float4 b0 = *(float4*)(&Bs[kk][tx * 8]);
            float4 b1 = *(float4*)(&Bs[kk][tx * 8 + 4]);
            rb[0]=b0.x; rb[1]=b0.y; rb[2]=b0.z; rb[3]=b0.w;
            rb[4]=b1.x; rb[5]=b1.y; rb[6]=b1.z; rb[7]=b1.w;
#pragma unroll
            for (int i = 0; i < 8; i++)
#pragma unroll
                for (int j = 0; j < 8; j++)
                    acc[i][j] += ra[i] * rb[j];
        }
        __syncthreads();
    }

#pragma unroll
    for (int i = 0; i < 8; i++) {
        float* crow = C + (size_t)(rowBase + ty * 8 + i) * N + colBase + tx * 8;
        *(float4*)(crow)     = make_float4(acc[i][0], acc[i][1], acc[i][2], acc[i][3]);
        *(float4*)(crow + 4) = make_float4(acc[i][4], acc[i][5], acc[i][6], acc[i][7]);
    }
}

// ---------------- Causal flash attention, fp32 ----------------
// One CTA per (b, h, 64-row q tile). 256 threads: 4 lanes per q row,
// each lane owns a 16-wide chunk of d. Scores (64/row) live in registers,
// replicated across the 4 lanes via shfl reduction. K/V tiles in smem.
// NOTE: reference applies softmax FIRST, then divides by sqrt(DH)=8.
#define TQ 64
#define TK 64

__global__ __launch_bounds__(256) void attn_kernel(
    const float* __restrict__ qh, const float* __restrict__ kh,
    const float* __restrict__ vh, float* __restrict__ outp)
{
    int bh = blockIdx.y;             // 0..31
    int b = bh >> 4;                 // /H_
    int h = bh & 15;
    int qt = (L_ / TQ - 1) - blockIdx.x;   // heavy tiles first
    int q0 = qt * TQ;

    int tid = threadIdx.x;
    int r = tid >> 2;                // 0..63  q-row within tile
    int c = tid & 3;                 // 0..3   d-chunk
    int qi = q0 + r;

    const size_t base = ((size_t)b * L_) * DM + (size_t)h * DH;

    // Q row chunk in registers
    float Qc[16];
    {
        const float* qp = qh + base + (size_t)qi * DM + c * 16;
#pragma unroll
        for (int i = 0; i < 16; i += 4) {
            float4 t = *(const float4*)(qp + i);
            Qc[i] = t.x; Qc[i+1] = t.y; Qc[i+2] = t.z; Qc[i+3] = t.w;
        }
    }

    __shared__ float Ks[TK][DH];
    __shared__ float Vs[TK][DH];

    float O[16];
#pragma unroll
    for (int i = 0; i < 16; i++) O[i] = 0.f;
    float m = -1e30f, l = 0.f;

    int ntiles = q0 / TK + 1;
    for (int t = 0; t < ntiles; t++) {
        int k0 = t * TK;
        __syncthreads();   // protect previous iteration's smem reads
        {
            int lr = tid >> 4;       // 0..15
            int lc = tid & 15;       // float4 col 0..15
#pragma unroll
            for (int i = 0; i < 4; i++) {
                int row = lr + i * 16;
                const float* kp = kh + base + (size_t)(k0 + row) * DM + lc * 4;
                *(float4*)&Ks[row][lc * 4] = *(const float4*)kp;
                const float* vp = vh + base + (size_t)(k0 + row) * DM + lc * 4;
                *(float4*)&Vs[row][lc * 4] = *(const float4*)vp;
            }
        }
        __syncthreads();

        // Partial scores over this lane's 16-d chunk, all 64 keys
        float s[64];
#pragma unroll
        for (int k = 0; k < 64; k++) {
            float a = 0.f;
#pragma unroll
            for (int i = 0; i < 16; i++) a += Qc[i] * Ks[k][c * 16 + i];
            s[k] = a;
        }
        // reduce across the 4 lanes of this row -> every lane has full scores
#pragma unroll
        for (int k = 0; k < 64; k++) {
            s[k] += __shfl_xor_sync(0xffffffffu, s[k], 1);
            s[k] += __shfl_xor_sync(0xffffffffu, s[k], 2);
        }
        // causal mask + tile max
        float tm = -1e30f;
#pragma unroll
        for (int k = 0; k < 64; k++) {
            if (k0 + k > qi) s[k] = -1e9f;
            tm = fmaxf(tm, s[k]);
        }
        float mnew = fmaxf(m, tm);
        float corr = __expf(m - mnew);
        float psum = 0.f;
#pragma unroll
        for (int k = 0; k < 64; k++) {
            s[k] = __expf(s[k] - mnew);
            psum += s[k];
        }
        l = l * corr + psum;
        m = mnew;
#pragma unroll
        for (int i = 0; i < 16; i++) O[i] *= corr;
#pragma unroll
        for (int k = 0; k < 64; k++) {
            float p = s[k];
#pragma unroll
            for (int i = 0; i < 16; i++) O[i] += p * Vs[k][c * 16 + i];
        }
    }

    // softmax-then-scale quirk: divide by l AND by sqrt(DH)=8
    float inv = 1.f / (l * 8.0f);
    float* op = outp + base + (size_t)qi * DM + c * 16;
#pragma unroll
    for (int i = 0; i < 16; i += 4) {
        float4 t = make_float4(O[i] * inv, O[i+1] * inv, O[i+2] * inv, O[i+3] * inv);
        *(float4*)(op + i) = t;
    }
}

// ---------------- launch ----------------
extern "C" void kernel_launch(void* const* d_in, const int* in_sizes, int n_in,
                              void* d_out, int out_size)
{
    const float* q  = (const float*)d_in[0];
    const float* k  = (const float*)d_in[1];
    const float* v  = (const float*)d_in[2];
    // d_in[3] is the causal mask -> handled analytically
    const float* Wq = (const float*)d_in[4];
    const float* Wk = (const float*)d_in[5];
    const float* Wv = (const float*)d_in[6];
    const float* Wo = (const float*)d_in[7];
    float* out = (float*)d_out;

    float *qh, *kh, *vh, *att;
    cudaGetSymbolAddress((void**)&qh,  g_qh);
    cudaGetSymbolAddress((void**)&kh,  g_kh);
    cudaGetSymbolAddress((void**)&vh,  g_vh);
    cudaGetSymbolAddress((void**)&att, g_att);

    dim3 gProj(DM / BN, MROWS / BM);   // (8, 32)
    sgemm_kernel<<<gProj, 256>>>(q, Wq, qh, MROWS, DM, DM);
    sgemm_kernel<<<gProj, 256>>>(k, Wk, kh, MROWS, DM, DM);
    sgemm_kernel<<<gProj, 256>>>(v, Wv, vh, MROWS, DM, DM);

    dim3 gAttn(L_ / TQ, B_ * H_);      // (32, 32)
    attn_kernel<<<gAttn, 256>>>(qh, kh, vh, att);

    sgemm_kernel<<<gProj, 256>>>(att, Wo, out, MROWS, DM, DM);
}

// round 5
// speedup vs baseline: 1.6579x; 1.6579x over previous
#include <cuda_runtime.h>
#include <cstddef>
#include <cstdint>

// Problem constants
#define B_ 2
#define L_ 2048
#define DM 1024
#define H_ 16
#define DH 64
#define MROWS (B_ * L_)   // 4096

// ---------------- scratch (no allocation allowed) ----------------
__device__ float g_qh[MROWS * DM];
__device__ float g_kh[MROWS * DM];
__device__ float g_vh[MROWS * DM];
__device__ float g_att[MROWS * DM];

// ---------------- tf32 helpers ----------------
__device__ __forceinline__ unsigned f2tf32(float x) {
    unsigned r;
    asm("cvt.rna.tf32.f32 %0, %1;" : "=r"(r) : "f"(x));
    return r;
}
__device__ __forceinline__ float tf32f(float x) {
    return __uint_as_float(f2tf32(x));
}
// split x into hi (tf32) and lo (tf32 of residual)
__device__ __forceinline__ void tf32split(float x, float& hi, float& lo) {
    hi = tf32f(x);
    lo = tf32f(x - hi);
}
__device__ __forceinline__ void mma_tf32(
    float& c0, float& c1, float& c2, float& c3,
    unsigned a0, unsigned a1, unsigned a2, unsigned a3,
    unsigned b0, unsigned b1)
{
    asm volatile(
        "mma.sync.aligned.m16n8k8.row.col.f32.tf32.tf32.f32 "
        "{%0,%1,%2,%3}, {%4,%5,%6,%7}, {%8,%9}, {%0,%1,%2,%3};"
        : "+f"(c0), "+f"(c1), "+f"(c2), "+f"(c3)
        : "r"(a0), "r"(a1), "r"(a2), "r"(a3), "r"(b0), "r"(b1));
}

// ---------------- 3xTF32 GEMM: C[M,N] = A[M,K] * B[K,N] ----------------
// 128x128x32 CTA tile, 256 threads = 8 warps (2 m x 4 n), warp tile 64x32.
// Split precision: C += Ahi*Bhi + Ahi*Blo + Alo*Bhi  (fp32-equivalent).
#define GBM 128
#define GBN 128
#define GBK 32
#define AS_STR 36
#define BS_STR 136
#define GEMM_SMEM ((2 * GBM * AS_STR + 2 * GBK * BS_STR) * 4)   // 71680 B

__global__ __launch_bounds__(256) void gemm_tf32x3(
    const float* __restrict__ A, const float* __restrict__ Bw,
    float* __restrict__ C, int M, int N, int K)
{
    extern __shared__ float smg[];
    float* AsH = smg;                        // [GBM][AS_STR]
    float* AsL = AsH + GBM * AS_STR;
    float* BsH = AsL + GBM * AS_STR;         // [GBK][BS_STR]
    float* BsL = BsH + GBK * BS_STR;

    int tid  = threadIdx.x;
    int lane = tid & 31;
    int warp = tid >> 5;
    int wm = warp & 1;
    int wn = warp >> 1;
    int g  = lane >> 2;
    int tg = lane & 3;
    int rowBase = blockIdx.y * GBM;
    int colBase = blockIdx.x * GBN;

    float acc[4][4][4];
#pragma unroll
    for (int mt = 0; mt < 4; mt++)
#pragma unroll
        for (int nt = 0; nt < 4; nt++)
#pragma unroll
            for (int i = 0; i < 4; i++) acc[mt][nt][i] = 0.f;

    for (int k0 = 0; k0 < K; k0 += GBK) {
#pragma unroll
        for (int it = 0; it < 4; it++) {
            int idx = tid + it * 256;       // 0..1023
            // A tile: 128 rows x 8 float4
            int ar = idx >> 3, ac4 = idx & 7;
            float4 a = *(const float4*)(A + (size_t)(rowBase + ar) * K + k0 + ac4 * 4);
            float4 ah, al;
            tf32split(a.x, ah.x, al.x); tf32split(a.y, ah.y, al.y);
            tf32split(a.z, ah.z, al.z); tf32split(a.w, ah.w, al.w);
            *(float4*)&AsH[ar * AS_STR + ac4 * 4] = ah;
            *(float4*)&AsL[ar * AS_STR + ac4 * 4] = al;
            // B tile: 32 rows x 32 float4
            int br = idx >> 5, bc4 = idx & 31;
            float4 b = *(const float4*)(Bw + (size_t)(k0 + br) * N + colBase + bc4 * 4);
            float4 bh, bl;
            tf32split(b.x, bh.x, bl.x); tf32split(b.y, bh.y, bl.y);
            tf32split(b.z, bh.z, bl.z); tf32split(b.w, bh.w, bl.w);
            *(float4*)&BsH[br * BS_STR + bc4 * 4] = bh;
            *(float4*)&BsL[br * BS_STR + bc4 * 4] = bl;
        }
        __syncthreads();

#pragma unroll
        for (int ks = 0; ks < 4; ks++) {
            int kk = ks * 8 + tg;
            unsigned afH[4][4], afL[4][4];
#pragma unroll
            for (int mt = 0; mt < 4; mt++) {
                int m = wm * 64 + mt * 16 + g;
                afH[mt][0] = __float_as_uint(AsH[m * AS_STR + kk]);
                afH[mt][1] = __float_as_uint(AsH[(m + 8) * AS_STR + kk]);
                afH[mt][2] = __float_as_uint(AsH[m * AS_STR + kk + 4]);
                afH[mt][3] = __float_as_uint(AsH[(m + 8) * AS_STR + kk + 4]);
                afL[mt][0] = __float_as_uint(AsL[m * AS_STR + kk]);
                afL[mt][1] = __float_as_uint(AsL[(m + 8) * AS_STR + kk]);
                afL[mt][2] = __float_as_uint(AsL[m * AS_STR + kk + 4]);
                afL[mt][3] = __float_as_uint(AsL[(m + 8) * AS_STR + kk + 4]);
            }
            unsigned bfH[4][2], bfL[4][2];
#pragma unroll
            for (int nt = 0; nt < 4; nt++) {
                int n = wn * 32 + nt * 8 + g;
                bfH[nt][0] = __float_as_uint(BsH[kk * BS_STR + n]);
                bfH[nt][1] = __float_as_uint(BsH[(kk + 4) * BS_STR + n]);
                bfL[nt][0] = __float_as_uint(BsL[kk * BS_STR + n]);
                bfL[nt][1] = __float_as_uint(BsL[(kk + 4) * BS_STR + n]);
            }
#pragma unroll
            for (int mt = 0; mt < 4; mt++)
#pragma unroll
                for (int nt = 0; nt < 4; nt++) {
                    float* c = acc[mt][nt];
                    mma_tf32(c[0], c[1], c[2], c[3],
                             afH[mt][0], afH[mt][1], afH[mt][2], afH[mt][3],
                             bfL[nt][0], bfL[nt][1]);
                    mma_tf32(c[0], c[1], c[2], c[3],
                             afL[mt][0], afL[mt][1], afL[mt][2], afL[mt][3],
                             bfH[nt][0], bfH[nt][1]);
                    mma_tf32(c[0], c[1], c[2], c[3],
                             afH[mt][0], afH[mt][1], afH[mt][2], afH[mt][3],
                             bfH[nt][0], bfH[nt][1]);
                }
        }
        __syncthreads();
    }

#pragma unroll
    for (int mt = 0; mt < 4; mt++) {
#pragma unroll
        for (int nt = 0; nt < 4; nt++) {
            int r0 = rowBase + wm * 64 + mt * 16 + g;
            int cc = colBase + wn * 32 + nt * 8 + 2 * tg;
            *(float2*)(C + (size_t)r0 * N + cc)       = make_float2(acc[mt][nt][0], acc[mt][nt][1]);
            *(float2*)(C + (size_t)(r0 + 8) * N + cc) = make_float2(acc[mt][nt][2], acc[mt][nt][3]);
        }
    }
}

// ---------------- 3xTF32 flash attention (causal) ----------------
// CTA per (b, h, 64-row q tile). 128 threads = 4 warps, warp owns 16 q rows.
// All matmuls split-precision. Reference quirk: softmax FIRST, then /sqrt(DH)=8.
#define TQ 64
#define KS_STR 68
#define PS_STR 68
#define VS_STR 72
#define ATTN_SMEM ((2 * 64 * KS_STR + 2 * 64 * PS_STR + 2 * 64 * VS_STR) * 4)  // 106496 B

__global__ __launch_bounds__(128) void attn_tf32x3(
    const float* __restrict__ qh, const float* __restrict__ kh,
    const float* __restrict__ vh, float* __restrict__ outp)
{
    extern __shared__ float sm[];
    float* KsH = sm;
    float* KsL = KsH + 64 * KS_STR;
    float* PsH = KsL + 64 * KS_STR;
    float* PsL = PsH + 64 * PS_STR;
    float* VsH = PsL + 64 * PS_STR;
    float* VsL = VsH + 64 * VS_STR;

    int bh = blockIdx.y;
    int b = bh >> 4;
    int h = bh & 15;
    int qt = (L_ / TQ - 1) - blockIdx.x;     // heavy tiles first
    int q0 = qt * TQ;

    int tid  = threadIdx.x;
    int lane = tid & 31;
    int warp = tid >> 5;
    int g  = lane >> 2;
    int tg = lane & 3;

    const size_t base = (size_t)b * L_ * DM + (size_t)h * DH;
    int r0 = q0 + warp * 16 + g;

    // Q fragments (hi/lo), register resident
    unsigned qaH[8][4], qaL[8][4];
    {
        const float* qp = qh + base;
#pragma unroll
        for (int kd = 0; kd < 8; kd++) {
            int c = kd * 8 + tg;
            float v0 = qp[(size_t)r0 * DM + c];
            float v1 = qp[(size_t)(r0 + 8) * DM + c];
            float v2 = qp[(size_t)r0 * DM + c + 4];
            float v3 = qp[(size_t)(r0 + 8) * DM + c + 4];
            float hi, lo;
            tf32split(v0, hi, lo); qaH[kd][0] = __float_as_uint(hi); qaL[kd][0] = __float_as_uint(lo);
            tf32split(v1, hi, lo); qaH[kd][1] = __float_as_uint(hi); qaL[kd][1] = __float_as_uint(lo);
            tf32split(v2, hi, lo); qaH[kd][2] = __float_as_uint(hi); qaL[kd][2] = __float_as_uint(lo);
            tf32split(v3, hi, lo); qaH[kd][3] = __float_as_uint(hi); qaL[kd][3] = __float_as_uint(lo);
        }
    }

    float o[8][4];
#pragma unroll
    for (int nd = 0; nd < 8; nd++)
#pragma unroll
        for (int i = 0; i < 4; i++) o[nd][i] = 0.f;
    float m0 = -1e30f, m1 = -1e30f, l0 = 0.f, l1 = 0.f;

    int ntiles = qt + 1;
    for (int t = 0; t < ntiles; t++) {
        int k0 = t * TQ;
        __syncthreads();
        // stage K,V tiles split into hi/lo
#pragma unroll
        for (int it = 0; it < 8; it++) {
            int idx = tid + it * 128;        // 0..1023
            int row = idx >> 4, c4 = idx & 15;
            float4 kv = *(const float4*)(kh + base + (size_t)(k0 + row) * DM + c4 * 4);
            float4 h4, l4;
            tf32split(kv.x, h4.x, l4.x); tf32split(kv.y, h4.y, l4.y);
            tf32split(kv.z, h4.z, l4.z); tf32split(kv.w, h4.w, l4.w);
            *(float4*)&KsH[row * KS_STR + c4 * 4] = h4;
            *(float4*)&KsL[row * KS_STR + c4 * 4] = l4;
            float4 vv = *(const float4*)(vh + base + (size_t)(k0 + row) * DM + c4 * 4);
            tf32split(vv.x, h4.x, l4.x); tf32split(vv.y, h4.y, l4.y);
            tf32split(vv.z, h4.z, l4.z); tf32split(vv.w, h4.w, l4.w);
            *(float4*)&VsH[row * VS_STR + c4 * 4] = h4;
            *(float4*)&VsL[row * VS_STR + c4 * 4] = l4;
        }
        __syncthreads();

        // scores: 16 x 64 per warp
        float s[8][4];
#pragma unroll
        for (int nt = 0; nt < 8; nt++)
#pragma unroll
            for (int i = 0; i < 4; i++) s[nt][i] = 0.f;

#pragma unroll
        for (int kd = 0; kd < 8; kd++) {
            int kk = kd * 8 + tg;
#pragma unroll
            for (int nt = 0; nt < 8; nt++) {
                int nrow = nt * 8 + g;
                unsigned bH0 = __float_as_uint(KsH[nrow * KS_STR + kk]);
                unsigned bH1 = __float_as_uint(KsH[nrow * KS_STR + kk + 4]);
                unsigned bL0 = __float_as_uint(KsL[nrow * KS_STR + kk]);
                unsigned bL1 = __float_as_uint(KsL[nrow * KS_STR + kk + 4]);
                float* c = s[nt];
                mma_tf32(c[0], c[1], c[2], c[3],
                         qaH[kd][0], qaH[kd][1], qaH[kd][2], qaH[kd][3], bL0, bL1);
                mma_tf32(c[0], c[1], c[2], c[3],
                         qaL[kd][0], qaL[kd][1], qaL[kd][2], qaL[kd][3], bH0, bH1);
                mma_tf32(c[0], c[1], c[2], c[3],
                         qaH[kd][0], qaH[kd][1], qaH[kd][2], qaH[kd][3], bH0, bH1);
            }
        }

        // causal mask (only the diagonal tile)
        if (t == ntiles - 1) {
#pragma unroll
            for (int nt = 0; nt < 8; nt++) {
                int col = k0 + nt * 8 + 2 * tg;
                if (col     > r0)     s[nt][0] = -1e9f;
                if (col + 1 > r0)     s[nt][1] = -1e9f;
                if (col     > r0 + 8) s[nt][2] = -1e9f;
                if (col + 1 > r0 + 8) s[nt][3] = -1e9f;
            }
        }

        // online softmax (2 rows per thread)
        float mx0 = -1e30f, mx1 = -1e30f;
#pragma unroll
        for (int nt = 0; nt < 8; nt++) {
            mx0 = fmaxf(mx0, fmaxf(s[nt][0], s[nt][1]));
            mx1 = fmaxf(mx1, fmaxf(s[nt][2], s[nt][3]));
        }
        mx0 = fmaxf(mx0, __shfl_xor_sync(0xffffffffu, mx0, 1));
        mx0 = fmaxf(mx0, __shfl_xor_sync(0xffffffffu, mx0, 2));
        mx1 = fmaxf(mx1, __shfl_xor_sync(0xffffffffu, mx1, 1));
        mx1 = fmaxf(mx1, __shfl_xor_sync(0xffffffffu, mx1, 2));

        float mn0 = fmaxf(m0, mx0), mn1 = fmaxf(m1, mx1);
        float cr0 = __expf(m0 - mn0), cr1 = __expf(m1 - mn1);
        float sum0 = 0.f, sum1 = 0.f;
        int prow = warp * 16 + g;
#pragma unroll
        for (int nt = 0; nt < 8; nt++) {
            float p0 = __expf(s[nt][0] - mn0);
            float p1 = __expf(s[nt][1] - mn0);
            float p2 = __expf(s[nt][2] - mn1);
            float p3 = __expf(s[nt][3] - mn1);
            sum0 += p0 + p1;
            sum1 += p2 + p3;
            float hi, lo;
            float2 h2, l2;
            tf32split(p0, hi, lo); h2.x = hi; l2.x = lo;
            tf32split(p1, hi, lo); h2.y = hi; l2.y = lo;
            *(float2*)&PsH[prow * PS_STR + nt * 8 + 2 * tg] = h2;
            *(float2*)&PsL[prow * PS_STR + nt * 8 + 2 * tg] = l2;
            tf32split(p2, hi, lo); h2.x = hi; l2.x = lo;
            tf32split(p3, hi, lo); h2.y = hi; l2.y = lo;
            *(float2*)&PsH[(prow + 8) * PS_STR + nt * 8 + 2 * tg] = h2;
            *(float2*)&PsL[(prow + 8) * PS_STR + nt * 8 + 2 * tg] = l2;
        }
        sum0 += __shfl_xor_sync(0xffffffffu, sum0, 1);
        sum0 += __shfl_xor_sync(0xffffffffu, sum0, 2);
        sum1 += __shfl_xor_sync(0xffffffffu, sum1, 1);
        sum1 += __shfl_xor_sync(0xffffffffu, sum1, 2);
        l0 = l0 * cr0 + sum0;
        l1 = l1 * cr1 + sum1;
        m0 = mn0; m1 = mn1;

#pragma unroll
        for (int nd = 0; nd < 8; nd++) {
            o[nd][0] *= cr0; o[nd][1] *= cr0;
            o[nd][2] *= cr1; o[nd][3] *= cr1;
        }
        __syncwarp();   // Ps stores -> cross-lane Ps loads (warp-private rows)

        // PV: P(16x64) x V(64x64) split-precision
#pragma unroll
        for (int ks = 0; ks < 8; ks++) {
            int kk = ks * 8 + tg;
            int pr = warp * 16 + g;
            unsigned pH0 = __float_as_uint(PsH[pr * PS_STR + kk]);
            unsigned pH1 = __float_as_uint(PsH[(pr + 8) * PS_STR + kk]);
            unsigned pH2 = __float_as_uint(PsH[pr * PS_STR + kk + 4]);
            unsigned pH3 = __float_as_uint(PsH[(pr + 8) * PS_STR + kk + 4]);
            unsigned pL0 = __float_as_uint(PsL[pr * PS_STR + kk]);
            unsigned pL1 = __float_as_uint(PsL[(pr + 8) * PS_STR + kk]);
            unsigned pL2 = __float_as_uint(PsL[pr * PS_STR + kk + 4]);
            unsigned pL3 = __float_as_uint(PsL[(pr + 8) * PS_STR + kk + 4]);
#pragma unroll
            for (int nd = 0; nd < 8; nd++) {
                unsigned vH0 = __float_as_uint(VsH[kk * VS_STR + nd * 8 + g]);
                unsigned vH1 = __float_as_uint(VsH[(kk + 4) * VS_STR + nd * 8 + g]);
                unsigned vL0 = __float_as_uint(VsL[kk * VS_STR + nd * 8 + g]);
                unsigned vL1 = __float_as_uint(VsL[(kk + 4) * VS_STR + nd * 8 + g]);
                float* c = o[nd];
                mma_tf32(c[0], c[1], c[2], c[3], pH0, pH1, pH2, pH3, vL0, vL1);
                mma_tf32(c[0], c[1], c[2], c[3], pL0, pL1, pL2, pL3, vH0, vH1);
                mma_tf32(c[0], c[1], c[2], c[3], pH0, pH1, pH2, pH3, vH0, vH1);
            }
        }
    }

    // softmax-then-scale quirk: divide by l AND by sqrt(DH)=8
    float inv0 = 1.f / (l0 * 8.f);
    float inv1 = 1.f / (l1 * 8.f);
#pragma unroll
    for (int nd = 0; nd < 8; nd++) {
        int cc = nd * 8 + 2 * tg;
        *(float2*)(outp + base + (size_t)r0 * DM + cc) =
            make_float2(o[nd][0] * inv0, o[nd][1] * inv0);
        *(float2*)(outp + base + (size_t)(r0 + 8) * DM + cc) =
            make_float2(o[nd][2] * inv1, o[nd][3] * inv1);
    }
}

// ---------------- launch ----------------
extern "C" void kernel_launch(void* const* d_in, const int* in_sizes, int n_in,
                              void* d_out, int out_size)
{
    const float* q  = (const float*)d_in[0];
    const float* k  = (const float*)d_in[1];
    const float* v  = (const float*)d_in[2];
    // d_in[3] is the causal mask -> handled analytically
    const float* Wq = (const float*)d_in[4];
    const float* Wk = (const float*)d_in[5];
    const float* Wv = (const float*)d_in[6];
    const float* Wo = (const float*)d_in[7];
    float* out = (float*)d_out;

    float *qh, *kh, *vh, *att;
    cudaGetSymbolAddress((void**)&qh,  g_qh);
    cudaGetSymbolAddress((void**)&kh,  g_kh);
    cudaGetSymbolAddress((void**)&vh,  g_vh);
    cudaGetSymbolAddress((void**)&att, g_att);

    static int smem_set = 0;
    if (!smem_set) {
        cudaFuncSetAttribute(gemm_tf32x3, cudaFuncAttributeMaxDynamicSharedMemorySize, GEMM_SMEM);
        cudaFuncSetAttribute(attn_tf32x3, cudaFuncAttributeMaxDynamicSharedMemorySize, ATTN_SMEM);
        smem_set = 1;
    }

    dim3 gProj(DM / GBN, MROWS / GBM);   // (8, 32)
    gemm_tf32x3<<<gProj, 256, GEMM_SMEM>>>(q, Wq, qh, MROWS, DM, DM);
    gemm_tf32x3<<<gProj, 256, GEMM_SMEM>>>(k, Wk, kh, MROWS, DM, DM);
    gemm_tf32x3<<<gProj, 256, GEMM_SMEM>>>(v, Wv, vh, MROWS, DM, DM);

    dim3 gAttn(L_ / TQ, B_ * H_);        // (32, 32)
    attn_tf32x3<<<gAttn, 128, ATTN_SMEM>>>(qh, kh, vh, att);

    gemm_tf32x3<<<gProj, 256, GEMM_SMEM>>>(att, Wo, out, MROWS, DM, DM);
}

// round 9
// speedup vs baseline: 2.6923x; 1.6239x over previous
#include <cuda_runtime.h>
#include <cstddef>
#include <cstdint>

// Problem constants
#define B_ 2
#define L_ 2048
#define DM 1024
#define H_ 16
#define DH 64
#define MROWS (B_ * L_)   // 4096

// ---------------- scratch (no allocation allowed) ----------------
__device__ float g_qh[MROWS * DM];
__device__ float g_kh[MROWS * DM];
__device__ float g_vh[MROWS * DM];
__device__ float g_att[MROWS * DM];

// ---------------- tf32 helpers ----------------
__device__ __forceinline__ unsigned f2tf32(float x) {
    unsigned r;
    asm("cvt.rna.tf32.f32 %0, %1;" : "=r"(r) : "f"(x));
    return r;
}
__device__ __forceinline__ float tf32f(float x) {
    return __uint_as_float(f2tf32(x));
}
// split raw fp32 -> (hi tf32, lo tf32) as uint bit patterns
__device__ __forceinline__ void splitu(float x, unsigned& h, unsigned& l) {
    float hf = tf32f(x);
    h = __float_as_uint(hf);
    l = f2tf32(x - hf);
}
__device__ __forceinline__ void mma_tf32(
    float& c0, float& c1, float& c2, float& c3,
    unsigned a0, unsigned a1, unsigned a2, unsigned a3,
    unsigned b0, unsigned b1)
{
    asm volatile(
        "mma.sync.aligned.m16n8k8.row.col.f32.tf32.tf32.f32 "
        "{%0,%1,%2,%3}, {%4,%5,%6,%7}, {%8,%9}, {%0,%1,%2,%3};"
        : "+f"(c0), "+f"(c1), "+f"(c2), "+f"(c3)
        : "r"(a0), "r"(a1), "r"(a2), "r"(a3), "r"(b0), "r"(b1));
}

// ---------------- cp.async helpers ----------------
__device__ __forceinline__ void cp_async16(void* smem_ptr, const void* gptr) {
    unsigned saddr = (unsigned)__cvta_generic_to_shared(smem_ptr);
    asm volatile("cp.async.cg.shared.global [%0], [%1], 16;\n"
                 :: "r"(saddr), "l"(gptr));
}
__device__ __forceinline__ void cp_commit() {
    asm volatile("cp.async.commit_group;\n");
}
template<int N> __device__ __forceinline__ void cp_wait() {
    asm volatile("cp.async.wait_group %0;\n" :: "n"(N));
}

// ---------------- 3xTF32 GEMM with cp.async double buffer ----------------
// C[M,N] = A[M,K] * B[K,N]. 128x128x32 CTA tile, 256 threads = 8 warps (2m x 4n).
// Raw fp32 tiles staged via cp.async; hi/lo split at fragment load.
#define GBM 128
#define GBN 128
#define GBK 32
#define AS_STR 36
#define BS_STR 136
#define A_TILE (GBM * AS_STR)
#define B_TILE (GBK * BS_STR)
#define STAGE_F (A_TILE + B_TILE)             // floats per stage
#define GEMM_SMEM (2 * STAGE_F * 4)           // 71680 B

__global__ __launch_bounds__(256) void gemm_tf32x3(
    const float* __restrict__ A, const float* __restrict__ Bw,
    float* __restrict__ C, int M, int N, int K)
{
    extern __shared__ float smg[];

    int tid  = threadIdx.x;
    int lane = tid & 31;
    int warp = tid >> 5;
    int wm = warp & 1;
    int wn = warp >> 1;
    int g  = lane >> 2;
    int tg = lane & 3;
    int rowBase = blockIdx.y * GBM;
    int colBase = blockIdx.x * GBN;

    // stage loader: raw fp32, no conversion
    auto load_tile = [&](int k0, int s) {
        float* As = smg + s * STAGE_F;
        float* Bs = As + A_TILE;
#pragma unroll
        for (int it = 0; it < 4; it++) {
            int idx = tid + it * 256;           // 0..1023
            int ar = idx >> 3, ac4 = idx & 7;   // A: 128 x 8 float4
            cp_async16(&As[ar * AS_STR + ac4 * 4],
                       A + (size_t)(rowBase + ar) * K + k0 + ac4 * 4);
            int br = idx >> 5, bc4 = idx & 31;  // B: 32 x 32 float4
            cp_async16(&Bs[br * BS_STR + bc4 * 4],
                       Bw + (size_t)(k0 + br) * N + colBase + bc4 * 4);
        }
    };

    float acc[4][4][4];
#pragma unroll
    for (int mt = 0; mt < 4; mt++)
#pragma unroll
        for (int nt = 0; nt < 4; nt++)
#pragma unroll
            for (int i = 0; i < 4; i++) acc[mt][nt][i] = 0.f;

    int NT = K / GBK;
    load_tile(0, 0);
    cp_commit();

    for (int t = 0; t < NT; t++) {
        if (t + 1 < NT) load_tile((t + 1) * GBK, (t + 1) & 1);
        cp_commit();
        cp_wait<1>();
        __syncthreads();

        const float* As = smg + (t & 1) * STAGE_F;
        const float* Bs = As + A_TILE;

#pragma unroll
        for (int ks = 0; ks < 4; ks++) {
            int kk = ks * 8 + tg;
            unsigned afH[4][4], afL[4][4];
#pragma unroll
            for (int mt = 0; mt < 4; mt++) {
                int m = wm * 64 + mt * 16 + g;
                splitu(As[m * AS_STR + kk],           afH[mt][0], afL[mt][0]);
                splitu(As[(m + 8) * AS_STR + kk],     afH[mt][1], afL[mt][1]);
                splitu(As[m * AS_STR + kk + 4],       afH[mt][2], afL[mt][2]);
                splitu(As[(m + 8) * AS_STR + kk + 4], afH[mt][3], afL[mt][3]);
            }
            unsigned bfH[4][2], bfL[4][2];
#pragma unroll
            for (int nt = 0; nt < 4; nt++) {
                int n = wn * 32 + nt * 8 + g;
                splitu(Bs[kk * BS_STR + n],       bfH[nt][0], bfL[nt][0]);
                splitu(Bs[(kk + 4) * BS_STR + n], bfH[nt][1], bfL[nt][1]);
            }
#pragma unroll
            for (int mt = 0; mt < 4; mt++)
#pragma unroll
                for (int nt = 0; nt < 4; nt++) {
                    float* c = acc[mt][nt];
                    mma_tf32(c[0], c[1], c[2], c[3],
                             afH[mt][0], afH[mt][1], afH[mt][2], afH[mt][3],
                             bfL[nt][0], bfL[nt][1]);
                    mma_tf32(c[0], c[1], c[2], c[3],
                             afL[mt][0], afL[mt][1], afL[mt][2], afL[mt][3],
                             bfH[nt][0], bfH[nt][1]);
                    mma_tf32(c[0], c[1], c[2], c[3],
                             afH[mt][0], afH[mt][1], afH[mt][2], afH[mt][3],
                             bfH[nt][0], bfH[nt][1]);
                }
        }
        __syncthreads();   // reads done before next iter's cp.async overwrites
    }

#pragma unroll
    for (int mt = 0; mt < 4; mt++) {
#pragma unroll
        for (int nt = 0; nt < 4; nt++) {
            int r0 = rowBase + wm * 64 + mt * 16 + g;
            int cc = colBase + wn * 32 + nt * 8 + 2 * tg;
            *(float2*)(C + (size_t)r0 * N + cc)       = make_float2(acc[mt][nt][0], acc[mt][nt][1]);
            *(float2*)(C + (size_t)(r0 + 8) * N + cc) = make_float2(acc[mt][nt][2], acc[mt][nt][3]);
        }
    }
}

// ---------------- 3xTF32 flash attention (causal) ----------------
// CTA per (b, h, 64-row q tile). 128 threads = 4 warps, warp owns 16 q rows.
// Raw K/V staged via cp.async double-buffer; split at fragment load.
// P converted accumulator->A-fragment via shfl (no smem round-trip).
// Reference quirk: softmax FIRST, then /sqrt(DH)=8.
#define TQ 64
#define KS_STR 68
#define VS_STR 72
#define K_TILE (64 * KS_STR)
#define V_TILE (64 * VS_STR)
#define AST_F (K_TILE + V_TILE)
#define ATTN_SMEM (2 * AST_F * 4)    // 71680 B

__global__ __launch_bounds__(128) void attn_tf32x3(
    const float* __restrict__ qh, const float* __restrict__ kh,
    const float* __restrict__ vh, float* __restrict__ outp)
{
    extern __shared__ float sm[];

    int bh = blockIdx.y;
    int b = bh >> 4;
    int h = bh & 15;
    int qt = (L_ / TQ - 1) - blockIdx.x;     // heavy tiles first
    int q0 = qt * TQ;

    int tid  = threadIdx.x;
    int lane = tid & 31;
    int warp = tid >> 5;
    int g  = lane >> 2;
    int tg = lane & 3;

    const size_t base = (size_t)b * L_ * DM + (size_t)h * DH;
    int r0 = q0 + warp * 16 + g;

    auto load_kv = [&](int k0, int s) {
        float* Ks = sm + s * AST_F;
        float* Vs = Ks + K_TILE;
#pragma unroll
        for (int it = 0; it < 8; it++) {
            int idx = tid + it * 128;        // 0..1023
            int row = idx >> 4, c4 = idx & 15;
            cp_async16(&Ks[row * KS_STR + c4 * 4],
                       kh + base + (size_t)(k0 + row) * DM + c4 * 4);
            cp_async16(&Vs[row * VS_STR + c4 * 4],
                       vh + base + (size_t)(k0 + row) * DM + c4 * 4);
        }
    };

    // Q fragments (hi/lo), register resident
    unsigned qaH[8][4], qaL[8][4];
    {
        const float* qp = qh + base;
#pragma unroll
        for (int kd = 0; kd < 8; kd++) {
            int c = kd * 8 + tg;
            splitu(qp[(size_t)r0 * DM + c],           qaH[kd][0], qaL[kd][0]);
            splitu(qp[(size_t)(r0 + 8) * DM + c],     qaH[kd][1], qaL[kd][1]);
            splitu(qp[(size_t)r0 * DM + c + 4],       qaH[kd][2], qaL[kd][2]);
            splitu(qp[(size_t)(r0 + 8) * DM + c + 4], qaH[kd][3], qaL[kd][3]);
        }
    }

    float o[8][4];
#pragma unroll
    for (int nd = 0; nd < 8; nd++)
#pragma unroll
        for (int i = 0; i < 4; i++) o[nd][i] = 0.f;
    float m0 = -1e30f, m1 = -1e30f, l0s = 0.f, l1s = 0.f;

    int ntiles = qt + 1;
    load_kv(0, 0);
    cp_commit();

    for (int t = 0; t < ntiles; t++) {
        if (t + 1 < ntiles) load_kv((t + 1) * TQ, (t + 1) & 1);
        cp_commit();
        cp_wait<1>();
        __syncthreads();

        const float* Ks = sm + (t & 1) * AST_F;
        const float* Vs = Ks + K_TILE;
        int k0 = t * TQ;

        // scores: 16 x 64 per warp
        float s[8][4];
#pragma unroll
        for (int nt = 0; nt < 8; nt++)
#pragma unroll
            for (int i = 0; i < 4; i++) s[nt][i] = 0.f;

#pragma unroll
        for (int kd = 0; kd < 8; kd++) {
            int kk = kd * 8 + tg;
#pragma unroll
            for (int nt = 0; nt < 8; nt++) {
                int nrow = nt * 8 + g;
                unsigned bH0, bL0, bH1, bL1;
                splitu(Ks[nrow * KS_STR + kk],     bH0, bL0);
                splitu(Ks[nrow * KS_STR + kk + 4], bH1, bL1);
                float* c = s[nt];
                mma_tf32(c[0], c[1], c[2], c[3],
                         qaH[kd][0], qaH[kd][1], qaH[kd][2], qaH[kd][3], bL0, bL1);
                mma_tf32(c[0], c[1], c[2], c[3],
                         qaL[kd][0], qaL[kd][1], qaL[kd][2], qaL[kd][3], bH0, bH1);
                mma_tf32(c[0], c[1], c[2], c[3],
                         qaH[kd][0], qaH[kd][1], qaH[kd][2], qaH[kd][3], bH0, bH1);
            }
        }

        // causal mask (only the diagonal tile)
        if (t == ntiles - 1) {
#pragma unroll
            for (int nt = 0; nt < 8; nt++) {
                int col = k0 + nt * 8 + 2 * tg;
                if (col     > r0)     s[nt][0] = -1e9f;
                if (col + 1 > r0)     s[nt][1] = -1e9f;
                if (col     > r0 + 8) s[nt][2] = -1e9f;
                if (col + 1 > r0 + 8) s[nt][3] = -1e9f;
            }
        }

        // online softmax (2 rows per thread)
        float mx0 = -1e30f, mx1 = -1e30f;
#pragma unroll
        for (int nt = 0; nt < 8; nt++) {
            mx0 = fmaxf(mx0, fmaxf(s[nt][0], s[nt][1]));
            mx1 = fmaxf(mx1, fmaxf(s[nt][2], s[nt][3]));
        }
        mx0 = fmaxf(mx0, __shfl_xor_sync(0xffffffffu, mx0, 1));
        mx0 = fmaxf(mx0, __shfl_xor_sync(0xffffffffu, mx0, 2));
        mx1 = fmaxf(mx1, __shfl_xor_sync(0xffffffffu, mx1, 1));
        mx1 = fmaxf(mx1, __shfl_xor_sync(0xffffffffu, mx1, 2));

        float mn0 = fmaxf(m0, mx0), mn1 = fmaxf(m1, mx1);
        float cr0 = __expf(m0 - mn0), cr1 = __expf(m1 - mn1);
        float sum0 = 0.f, sum1 = 0.f;
#pragma unroll
        for (int nt = 0; nt < 8; nt++) {
            s[nt][0] = __expf(s[nt][0] - mn0);
            s[nt][1] = __expf(s[nt][1] - mn0);
            s[nt][2] = __expf(s[nt][2] - mn1);
            s[nt][3] = __expf(s[nt][3] - mn1);
            sum0 += s[nt][0] + s[nt][1];
            sum1 += s[nt][2] + s[nt][3];
        }
        sum0 += __shfl_xor_sync(0xffffffffu, sum0, 1);
        sum0 += __shfl_xor_sync(0xffffffffu, sum0, 2);
        sum1 += __shfl_xor_sync(0xffffffffu, sum1, 1);
        sum1 += __shfl_xor_sync(0xffffffffu, sum1, 2);
        l0s = l0s * cr0 + sum0;
        l1s = l1s * cr1 + sum1;
        m0 = mn0; m1 = mn1;

#pragma unroll
        for (int nd = 0; nd < 8; nd++) {
            o[nd][0] *= cr0; o[nd][1] *= cr0;
            o[nd][2] *= cr1; o[nd][3] *= cr1;
        }

        // PV: P(16x64) x V(64x64). Accumulator layout -> A-fragment via shfl.
        int lq = lane & ~3;                  // g*4
        int srcA = lq + (tg >> 1);           // holds cols {2*(tg>>1), +1}
        int srcB = srcA + 2;                 // holds cols {tg+4 side}
        bool odd = (tg & 1);
#pragma unroll
        for (int ks = 0; ks < 8; ks++) {
            float w00 = __shfl_sync(0xffffffffu, s[ks][0], srcA);
            float w01 = __shfl_sync(0xffffffffu, s[ks][1], srcA);
            float w02 = __shfl_sync(0xffffffffu, s[ks][2], srcA);
            float w03 = __shfl_sync(0xffffffffu, s[ks][3], srcA);
            float w10 = __shfl_sync(0xffffffffu, s[ks][0], srcB);
            float w11 = __shfl_sync(0xffffffffu, s[ks][1], srcB);
            float w12 = __shfl_sync(0xffffffffu, s[ks][2], srcB);
            float w13 = __shfl_sync(0xffffffffu, s[ks][3], srcB);
            float pa0f = odd ? w01 : w00;    // P[g][ks*8+tg]
            float pa1f = odd ? w03 : w02;    // P[g+8][ks*8+tg]
            float pa2f = odd ? w11 : w10;    // P[g][ks*8+tg+4]
            float pa3f = odd ? w13 : w12;    // P[g+8][ks*8+tg+4]
            unsigned pH0, pL0, pH1, pL1, pH2, pL2, pH3, pL3;
            splitu(pa0f, pH0, pL0);
            splitu(pa1f, pH1, pL1);
            splitu(pa2f, pH2, pL2);
            splitu(pa3f, pH3, pL3);

            int kk = ks * 8 + tg;
#pragma unroll
            for (int nd = 0; nd < 8; nd++) {
                unsigned vH0, vL0, vH1, vL1;
                splitu(Vs[kk * VS_STR + nd * 8 + g],       vH0, vL0);
                splitu(Vs[(kk + 4) * VS_STR + nd * 8 + g], vH1, vL1);
                float* c = o[nd];
                mma_tf32(c[0], c[1], c[2], c[3], pH0, pH1, pH2, pH3, vL0, vL1);
                mma_tf32(c[0], c[1], c[2], c[3], pL0, pL1, pL2, pL3, vH0, vH1);
                mma_tf32(c[0], c[1], c[2], c[3], pH0, pH1, pH2, pH3, vH0, vH1);
            }
        }
        __syncthreads();   // smem reads done before next iter's cp.async overwrite
    }

    // softmax-then-scale quirk: divide by l AND by sqrt(DH)=8
    float inv0 = 1.f / (l0s * 8.f);
    float inv1 = 1.f / (l1s * 8.f);
#pragma unroll
    for (int nd = 0; nd < 8; nd++) {
        int cc = nd * 8 + 2 * tg;
        *(float2*)(outp + base + (size_t)r0 * DM + cc) =
            make_float2(o[nd][0] * inv0, o[nd][1] * inv0);
        *(float2*)(outp + base + (size_t)(r0 + 8) * DM + cc) =
            make_float2(o[nd][2] * inv1, o[nd][3] * inv1);
    }
}

// ---------------- launch ----------------
extern "C" void kernel_launch(void* const* d_in, const int* in_sizes, int n_in,
                              void* d_out, int out_size)
{
    const float* q  = (const float*)d_in[0];
    const float* k  = (const float*)d_in[1];
    const float* v  = (const float*)d_in[2];
    // d_in[3] is the causal mask -> handled analytically
    const float* Wq = (const float*)d_in[4];
    const float* Wk = (const float*)d_in[5];
    const float* Wv = (const float*)d_in[6];
    const float* Wo = (const float*)d_in[7];
    float* out = (float*)d_out;

    float *qh, *kh, *vh, *att;
    cudaGetSymbolAddress((void**)&qh,  g_qh);
    cudaGetSymbolAddress((void**)&kh,  g_kh);
    cudaGetSymbolAddress((void**)&vh,  g_vh);
    cudaGetSymbolAddress((void**)&att, g_att);

    static int smem_set = 0;
    if (!smem_set) {
        cudaFuncSetAttribute(gemm_tf32x3, cudaFuncAttributeMaxDynamicSharedMemorySize, GEMM_SMEM);
        cudaFuncSetAttribute(attn_tf32x3, cudaFuncAttributeMaxDynamicSharedMemorySize, ATTN_SMEM);
        smem_set = 1;
    }

    dim3 gProj(DM / GBN, MROWS / GBM);   // (8, 32)
    gemm_tf32x3<<<gProj, 256, GEMM_SMEM>>>(q, Wq, qh, MROWS, DM, DM);
    gemm_tf32x3<<<gProj, 256, GEMM_SMEM>>>(k, Wk, kh, MROWS, DM, DM);
    gemm_tf32x3<<<gProj, 256, GEMM_SMEM>>>(v, Wv, vh, MROWS, DM, DM);

    dim3 gAttn(L_ / TQ, B_ * H_);        // (32, 32)
    attn_tf32x3<<<gAttn, 128, ATTN_SMEM>>>(qh, kh, vh, att);

    gemm_tf32x3<<<gProj, 256, GEMM_SMEM>>>(att, Wo, out, MROWS, DM, DM);
}

// round 10
// speedup vs baseline: 3.0026x; 1.1153x over previous
#include <cuda_runtime.h>
#include <cstddef>
#include <cstdint>

// Problem constants
#define B_ 2
#define L_ 2048
#define DM 1024
#define H_ 16
#define DH 64
#define MROWS (B_ * L_)   // 4096

// ---------------- scratch (no allocation allowed) ----------------
// pre-split inputs
__device__ float g_q_hi[MROWS * DM], g_q_lo[MROWS * DM];
__device__ float g_k_hi[MROWS * DM], g_k_lo[MROWS * DM];
__device__ float g_v_hi[MROWS * DM], g_v_lo[MROWS * DM];
__device__ float g_Wq_hi[DM * DM], g_Wq_lo[DM * DM];
__device__ float g_Wk_hi[DM * DM], g_Wk_lo[DM * DM];
__device__ float g_Wv_hi[DM * DM], g_Wv_lo[DM * DM];
__device__ float g_Wo_hi[DM * DM], g_Wo_lo[DM * DM];
// pre-split intermediates
__device__ float g_qh_hi[MROWS * DM], g_qh_lo[MROWS * DM];
__device__ float g_kh_hi[MROWS * DM], g_kh_lo[MROWS * DM];
__device__ float g_vh_hi[MROWS * DM], g_vh_lo[MROWS * DM];
__device__ float g_att_hi[MROWS * DM], g_att_lo[MROWS * DM];

// ---------------- tf32 helpers ----------------
__device__ __forceinline__ unsigned f2tf32(float x) {
    unsigned r;
    asm("cvt.rna.tf32.f32 %0, %1;" : "=r"(r) : "f"(x));
    return r;
}
__device__ __forceinline__ float tf32f(float x) {
    return __uint_as_float(f2tf32(x));
}
__device__ __forceinline__ void splitf(float x, float& h, float& l) {
    h = tf32f(x);
    l = __uint_as_float(f2tf32(x - h));
}
__device__ __forceinline__ void mma_tf32(
    float& c0, float& c1, float& c2, float& c3,
    unsigned a0, unsigned a1, unsigned a2, unsigned a3,
    unsigned b0, unsigned b1)
{
    asm volatile(
        "mma.sync.aligned.m16n8k8.row.col.f32.tf32.tf32.f32 "
        "{%0,%1,%2,%3}, {%4,%5,%6,%7}, {%8,%9}, {%0,%1,%2,%3};"
        : "+f"(c0), "+f"(c1), "+f"(c2), "+f"(c3)
        : "r"(a0), "r"(a1), "r"(a2), "r"(a3), "r"(b0), "r"(b1));
}

// ---------------- cp.async helpers ----------------
__device__ __forceinline__ void cp_async16(void* smem_ptr, const void* gptr) {
    unsigned saddr = (unsigned)__cvta_generic_to_shared(smem_ptr);
    asm volatile("cp.async.cg.shared.global [%0], [%1], 16;\n"
                 :: "r"(saddr), "l"(gptr));
}
__device__ __forceinline__ void cp_commit() {
    asm volatile("cp.async.commit_group;\n");
}
template<int N> __device__ __forceinline__ void cp_wait() {
    asm volatile("cp.async.wait_group %0;\n" :: "n"(N));
}

// ---------------- batched split pre-pass ----------------
struct SplitEnt { const float* s; float* h; float* l; int n4; };
struct SplitBatch { SplitEnt e[7]; };

__global__ __launch_bounds__(256) void split7(SplitBatch sb) {
    const SplitEnt& e = sb.e[blockIdx.z];
    int i = blockIdx.x * blockDim.x + threadIdx.x;
    if (i >= e.n4) return;
    float4 x = ((const float4*)e.s)[i];
    float4 h4, l4;
    splitf(x.x, h4.x, l4.x); splitf(x.y, h4.y, l4.y);
    splitf(x.z, h4.z, l4.z); splitf(x.w, h4.w, l4.w);
    ((float4*)e.h)[i] = h4;
    ((float4*)e.l)[i] = l4;
}

// ---------------- 3xTF32 GEMM, pre-split operands, batched ----------------
// C = A * B, A[M,K] row-major, B[K,N] row-major, all operands pre-split hi/lo.
// 128x128x32 CTA tile, 256 threads = 8 warps (2m x 4n). Double-buffered cp.async.
// writeSplit: 1 -> write C hi/lo planes; 0 -> write raw fp32 to C0.
#define GBM 128
#define GBN 128
#define GBK 32
#define AS_STR 36
#define BS_STR 136
#define A_TILE (GBM * AS_STR)                // 4608 floats per plane
#define B_TILE (GBK * BS_STR)                // 4352 floats per plane
#define STAGE_F (2 * (A_TILE + B_TILE))      // hi+lo planes
#define GEMM_SMEM (2 * STAGE_F * 4)          // 143360 B

struct GemmEnt { const float *Ah, *Al, *Bh, *Bl; float *C0, *C1; };
struct GemmBatch { GemmEnt e[3]; int writeSplit; };

__global__ __launch_bounds__(256) void gemm_ps(GemmBatch gb, int M, int N, int K)
{
    extern __shared__ float smg[];
    const GemmEnt& P = gb.e[blockIdx.z];

    int tid  = threadIdx.x;
    int lane = tid & 31;
    int warp = tid >> 5;
    int wm = warp & 1;
    int wn = warp >> 1;
    int g  = lane >> 2;
    int tg = lane & 3;
    int rowBase = blockIdx.y * GBM;
    int colBase = blockIdx.x * GBN;

    auto load_tile = [&](int k0, int s) {
        float* AsH = smg + s * STAGE_F;
        float* AsL = AsH + A_TILE;
        float* BsH = AsL + A_TILE;
        float* BsL = BsH + B_TILE;
#pragma unroll
        for (int it = 0; it < 4; it++) {
            int idx = tid + it * 256;           // 0..1023
            int ar = idx >> 3, ac4 = idx & 7;   // A: 128 x 8 float4
            size_t ga = (size_t)(rowBase + ar) * K + k0 + ac4 * 4;
            cp_async16(&AsH[ar * AS_STR + ac4 * 4], P.Ah + ga);
            cp_async16(&AsL[ar * AS_STR + ac4 * 4], P.Al + ga);
            int br = idx >> 5, bc4 = idx & 31;  // B: 32 x 32 float4
            size_t gbo = (size_t)(k0 + br) * N + colBase + bc4 * 4;
            cp_async16(&BsH[br * BS_STR + bc4 * 4], P.Bh + gbo);
            cp_async16(&BsL[br * BS_STR + bc4 * 4], P.Bl + gbo);
        }
    };

    float acc[4][4][4];
#pragma unroll
    for (int mt = 0; mt < 4; mt++)
#pragma unroll
        for (int nt = 0; nt < 4; nt++)
#pragma unroll
            for (int i = 0; i < 4; i++) acc[mt][nt][i] = 0.f;

    int NT = K / GBK;
    load_tile(0, 0);
    cp_commit();

    for (int t = 0; t < NT; t++) {
        if (t + 1 < NT) load_tile((t + 1) * GBK, (t + 1) & 1);
        cp_commit();
        cp_wait<1>();
        __syncthreads();

        const float* AsH = smg + (t & 1) * STAGE_F;
        const float* AsL = AsH + A_TILE;
        const float* BsH = AsL + A_TILE;
        const float* BsL = BsH + B_TILE;

#pragma unroll
        for (int ks = 0; ks < 4; ks++) {
            int kk = ks * 8 + tg;
            unsigned afH[4][4], afL[4][4];
#pragma unroll
            for (int mt = 0; mt < 4; mt++) {
                int m = wm * 64 + mt * 16 + g;
                afH[mt][0] = __float_as_uint(AsH[m * AS_STR + kk]);
                afH[mt][1] = __float_as_uint(AsH[(m + 8) * AS_STR + kk]);
                afH[mt][2] = __float_as_uint(AsH[m * AS_STR + kk + 4]);
                afH[mt][3] = __float_as_uint(AsH[(m + 8) * AS_STR + kk + 4]);
                afL[mt][0] = __float_as_uint(AsL[m * AS_STR + kk]);
                afL[mt][1] = __float_as_uint(AsL[(m + 8) * AS_STR + kk]);
                afL[mt][2] = __float_as_uint(AsL[m * AS_STR + kk + 4]);
                afL[mt][3] = __float_as_uint(AsL[(m + 8) * AS_STR + kk + 4]);
            }
            unsigned bfH[4][2], bfL[4][2];
#pragma unroll
            for (int nt = 0; nt < 4; nt++) {
                int n = wn * 32 + nt * 8 + g;
                bfH[nt][0] = __float_as_uint(BsH[kk * BS_STR + n]);
                bfH[nt][1] = __float_as_uint(BsH[(kk + 4) * BS_STR + n]);
                bfL[nt][0] = __float_as_uint(BsL[kk * BS_STR + n]);
                bfL[nt][1] = __float_as_uint(BsL[(kk + 4) * BS_STR + n]);
            }
#pragma unroll
            for (int mt = 0; mt < 4; mt++)
#pragma unroll
                for (int nt = 0; nt < 4; nt++) {
                    float* c = acc[mt][nt];
                    mma_tf32(c[0], c[1], c[2], c[3],
                             afH[mt][0], afH[mt][1], afH[mt][2], afH[mt][3],
                             bfL[nt][0], bfL[nt][1]);
                    mma_tf32(c[0], c[1], c[2], c[3],
                             afL[mt][0], afL[mt][1], afL[mt][2], afL[mt][3],
                             bfH[nt][0], bfH[nt][1]);
                    mma_tf32(c[0], c[1], c[2], c[3],
                             afH[mt][0], afH[mt][1], afH[mt][2], afH[mt][3],
                             bfH[nt][0], bfH[nt][1]);
                }
        }
        __syncthreads();
    }

#pragma unroll
    for (int mt = 0; mt < 4; mt++) {
#pragma unroll
        for (int nt = 0; nt < 4; nt++) {
            int r0 = rowBase + wm * 64 + mt * 16 + g;
            int cc = colBase + wn * 32 + nt * 8 + 2 * tg;
            float* c = acc[mt][nt];
            if (gb.writeSplit) {
                float h0, l0, h1, l1;
                splitf(c[0], h0, l0); splitf(c[1], h1, l1);
                *(float2*)(P.C0 + (size_t)r0 * N + cc) = make_float2(h0, h1);
                *(float2*)(P.C1 + (size_t)r0 * N + cc) = make_float2(l0, l1);
                splitf(c[2], h0, l0); splitf(c[3], h1, l1);
                *(float2*)(P.C0 + (size_t)(r0 + 8) * N + cc) = make_float2(h0, h1);
                *(float2*)(P.C1 + (size_t)(r0 + 8) * N + cc) = make_float2(l0, l1);
            } else {
                *(float2*)(P.C0 + (size_t)r0 * N + cc)       = make_float2(c[0], c[1]);
                *(float2*)(P.C0 + (size_t)(r0 + 8) * N + cc) = make_float2(c[2], c[3]);
            }
        }
    }
}

// ---------------- 3xTF32 flash attention (causal), pre-split K/V ----------------
// CTA per (b, h, 64-row q tile). 128 threads = 4 warps, warp owns 16 q rows.
// K/V hi/lo planes staged via cp.async double-buffer; zero conversion ALU in
// the mma loops. P (post-exp) split in registers; accum->A-frag via shfl.
// Epilogue writes att pre-split (hi/lo) for the output GEMM.
// Reference quirk: softmax FIRST, then /sqrt(DH)=8.
#define TQ 64
#define KS_STR 68
#define VS_STR 72
#define K_TILE (64 * KS_STR)                 // 4352
#define V_TILE (64 * VS_STR)                 // 4608
#define AST_F (2 * (K_TILE + V_TILE))        // hi+lo planes
#define ATTN_SMEM (2 * AST_F * 4)            // 143360 B

__global__ __launch_bounds__(128) void attn_ps(
    const float* __restrict__ qhH, const float* __restrict__ qhL,
    const float* __restrict__ khH, const float* __restrict__ khL,
    const float* __restrict__ vhH, const float* __restrict__ vhL,
    float* __restrict__ attH, float* __restrict__ attL)
{
    extern __shared__ float sm[];

    int bh = blockIdx.y;
    int b = bh >> 4;
    int h = bh & 15;
    int qt = (L_ / TQ - 1) - blockIdx.x;     // heavy tiles first
    int q0 = qt * TQ;

    int tid  = threadIdx.x;
    int lane = tid & 31;
    int warp = tid >> 5;
    int g  = lane >> 2;
    int tg = lane & 3;

    const size_t base = (size_t)b * L_ * DM + (size_t)h * DH;
    int r0 = q0 + warp * 16 + g;

    auto load_kv = [&](int k0, int s) {
        float* KsH = sm + s * AST_F;
        float* KsL = KsH + K_TILE;
        float* VsH = KsL + K_TILE;
        float* VsL = VsH + V_TILE;
#pragma unroll
        for (int it = 0; it < 8; it++) {
            int idx = tid + it * 128;        // 0..1023
            int row = idx >> 4, c4 = idx & 15;
            size_t go = base + (size_t)(k0 + row) * DM + c4 * 4;
            cp_async16(&KsH[row * KS_STR + c4 * 4], khH + go);
            cp_async16(&KsL[row * KS_STR + c4 * 4], khL + go);
            cp_async16(&VsH[row * VS_STR + c4 * 4], vhH + go);
            cp_async16(&VsL[row * VS_STR + c4 * 4], vhL + go);
        }
    };

    // Q fragments (hi/lo) straight from pre-split planes
    unsigned qaH[8][4], qaL[8][4];
#pragma unroll
    for (int kd = 0; kd < 8; kd++) {
        int c = kd * 8 + tg;
        size_t i0 = base + (size_t)r0 * DM + c;
        size_t i1 = base + (size_t)(r0 + 8) * DM + c;
        qaH[kd][0] = __float_as_uint(qhH[i0]);
        qaH[kd][1] = __float_as_uint(qhH[i1]);
        qaH[kd][2] = __float_as_uint(qhH[i0 + 4]);
        qaH[kd][3] = __float_as_uint(qhH[i1 + 4]);
        qaL[kd][0] = __float_as_uint(qhL[i0]);
        qaL[kd][1] = __float_as_uint(qhL[i1]);
        qaL[kd][2] = __float_as_uint(qhL[i0 + 4]);
        qaL[kd][3] = __float_as_uint(qhL[i1 + 4]);
    }

    float o[8][4];
#pragma unroll
    for (int nd = 0; nd < 8; nd++)
#pragma unroll
        for (int i = 0; i < 4; i++) o[nd][i] = 0.f;
    float m0 = -1e30f, m1 = -1e30f, l0s = 0.f, l1s = 0.f;

    int ntiles = qt + 1;
    load_kv(0, 0);
    cp_commit();

    for (int t = 0; t < ntiles; t++) {
        if (t + 1 < ntiles) load_kv((t + 1) * TQ, (t + 1) & 1);
        cp_commit();
        cp_wait<1>();
        __syncthreads();

        const float* KsH = sm + (t & 1) * AST_F;
        const float* KsL = KsH + K_TILE;
        const float* VsH = KsL + K_TILE;
        const float* VsL = VsH + V_TILE;
        int k0 = t * TQ;

        // scores: 16 x 64 per warp
        float s[8][4];
#pragma unroll
        for (int nt = 0; nt < 8; nt++)
#pragma unroll
            for (int i = 0; i < 4; i++) s[nt][i] = 0.f;

#pragma unroll
        for (int kd = 0; kd < 8; kd++) {
            int kk = kd * 8 + tg;
#pragma unroll
            for (int nt = 0; nt < 8; nt++) {
                int nrow = nt * 8 + g;
                unsigned bH0 = __float_as_uint(KsH[nrow * KS_STR + kk]);
                unsigned bH1 = __float_as_uint(KsH[nrow * KS_STR + kk + 4]);
                unsigned bL0 = __float_as_uint(KsL[nrow * KS_STR + kk]);
                unsigned bL1 = __float_as_uint(KsL[nrow * KS_STR + kk + 4]);
                float* c = s[nt];
                mma_tf32(c[0], c[1], c[2], c[3],
                         qaH[kd][0], qaH[kd][1], qaH[kd][2], qaH[kd][3], bL0, bL1);
                mma_tf32(c[0], c[1], c[2], c[3],
                         qaL[kd][0], qaL[kd][1], qaL[kd][2], qaL[kd][3], bH0, bH1);
                mma_tf32(c[0], c[1], c[2], c[3],
                         qaH[kd][0], qaH[kd][1], qaH[kd][2], qaH[kd][3], bH0, bH1);
            }
        }

        // causal mask (only the diagonal tile)
        if (t == ntiles - 1) {
#pragma unroll
            for (int nt = 0; nt < 8; nt++) {
                int col = k0 + nt * 8 + 2 * tg;
                if (col     > r0)     s[nt][0] = -1e9f;
                if (col + 1 > r0)     s[nt][1] = -1e9f;
                if (col     > r0 + 8) s[nt][2] = -1e9f;
                if (col + 1 > r0 + 8) s[nt][3] = -1e9f;
            }
        }

        // online softmax (2 rows per thread)
        float mx0 = -1e30f, mx1 = -1e30f;
#pragma unroll
        for (int nt = 0; nt < 8; nt++) {
            mx0 = fmaxf(mx0, fmaxf(s[nt][0], s[nt][1]));
            mx1 = fmaxf(mx1, fmaxf(s[nt][2], s[nt][3]));
        }
        mx0 = fmaxf(mx0, __shfl_xor_sync(0xffffffffu, mx0, 1));
        mx0 = fmaxf(mx0, __shfl_xor_sync(0xffffffffu, mx0, 2));
        mx1 = fmaxf(mx1, __shfl_xor_sync(0xffffffffu, mx1, 1));
        mx1 = fmaxf(mx1, __shfl_xor_sync(0xffffffffu, mx1, 2));

        float mn0 = fmaxf(m0, mx0), mn1 = fmaxf(m1, mx1);
        float cr0 = __expf(m0 - mn0), cr1 = __expf(m1 - mn1);
        float sum0 = 0.f, sum1 = 0.f;
#pragma unroll
        for (int nt = 0; nt < 8; nt++) {
            s[nt][0] = __expf(s[nt][0] - mn0);
            s[nt][1] = __expf(s[nt][1] - mn0);
            s[nt][2] = __expf(s[nt][2] - mn1);
            s[nt][3] = __expf(s[nt][3] - mn1);
            sum0 += s[nt][0] + s[nt][1];
            sum1 += s[nt][2] + s[nt][3];
        }
        sum0 += __shfl_xor_sync(0xffffffffu, sum0, 1);
        sum0 += __shfl_xor_sync(0xffffffffu, sum0, 2);
        sum1 += __shfl_xor_sync(0xffffffffu, sum1, 1);
        sum1 += __shfl_xor_sync(0xffffffffu, sum1, 2);
        l0s = l0s * cr0 + sum0;
        l1s = l1s * cr1 + sum1;
        m0 = mn0; m1 = mn1;

#pragma unroll
        for (int nd = 0; nd < 8; nd++) {
            o[nd][0] *= cr0; o[nd][1] *= cr0;
            o[nd][2] *= cr1; o[nd][3] *= cr1;
        }

        // PV: P(16x64) x V(64x64). Accumulator layout -> A-fragment via shfl.
        int lq = lane & ~3;
        int srcA = lq + (tg >> 1);
        int srcB = srcA + 2;
        bool odd = (tg & 1);
#pragma unroll
        for (int ks = 0; ks < 8; ks++) {
            float w00 = __shfl_sync(0xffffffffu, s[ks][0], srcA);
            float w01 = __shfl_sync(0xffffffffu, s[ks][1], srcA);
            float w02 = __shfl_sync(0xffffffffu, s[ks][2], srcA);
            float w03 = __shfl_sync(0xffffffffu, s[ks][3], srcA);
            float w10 = __shfl_sync(0xffffffffu, s[ks][0], srcB);
            float w11 = __shfl_sync(0xffffffffu, s[ks][1], srcB);
            float w12 = __shfl_sync(0xffffffffu, s[ks][2], srcB);
            float w13 = __shfl_sync(0xffffffffu, s[ks][3], srcB);
            float pa0f = odd ? w01 : w00;
            float pa1f = odd ? w03 : w02;
            float pa2f = odd ? w11 : w10;
            float pa3f = odd ? w13 : w12;
            float hF, lF;
            unsigned pH0, pL0, pH1, pL1, pH2, pL2, pH3, pL3;
            splitf(pa0f, hF, lF); pH0 = __float_as_uint(hF); pL0 = __float_as_uint(lF);
            splitf(pa1f, hF, lF); pH1 = __float_as_uint(hF); pL1 = __float_as_uint(lF);
            splitf(pa2f, hF, lF); pH2 = __float_as_uint(hF); pL2 = __float_as_uint(lF);
            splitf(pa3f, hF, lF); pH3 = __float_as_uint(hF); pL3 = __float_as_uint(lF);

            int kk = ks * 8 + tg;
#pragma unroll
            for (int nd = 0; nd < 8; nd++) {
                unsigned vH0 = __float_as_uint(VsH[kk * VS_STR + nd * 8 + g]);
                unsigned vH1 = __float_as_uint(VsH[(kk + 4) * VS_STR + nd * 8 + g]);
                unsigned vL0 = __float_as_uint(VsL[kk * VS_STR + nd * 8 + g]);
                unsigned vL1 = __float_as_uint(VsL[(kk + 4) * VS_STR + nd * 8 + g]);
                float* c = o[nd];
                mma_tf32(c[0], c[1], c[2], c[3], pH0, pH1, pH2, pH3, vL0, vL1);
                mma_tf32(c[0], c[1], c[2], c[3], pL0, pL1, pL2, pL3, vH0, vH1);
                mma_tf32(c[0], c[1], c[2], c[3], pH0, pH1, pH2, pH3, vH0, vH1);
            }
        }
        __syncthreads();   // smem reads done before next iter's cp.async overwrite
    }

    // softmax-then-scale quirk: divide by l AND by sqrt(DH)=8; write pre-split
    float inv0 = 1.f / (l0s * 8.f);
    float inv1 = 1.f / (l1s * 8.f);
#pragma unroll
    for (int nd = 0; nd < 8; nd++) {
        int cc = nd * 8 + 2 * tg;
        size_t i0 = base + (size_t)r0 * DM + cc;
        size_t i1 = base + (size_t)(r0 + 8) * DM + cc;
        float h0, l0, h1, l1;
        splitf(o[nd][0] * inv0, h0, l0); splitf(o[nd][1] * inv0, h1, l1);
        *(float2*)(attH + i0) = make_float2(h0, h1);
        *(float2*)(attL + i0) = make_float2(l0, l1);
        splitf(o[nd][2] * inv1, h0, l0); splitf(o[nd][3] * inv1, h1, l1);
        *(float2*)(attH + i1) = make_float2(h0, h1);
        *(float2*)(attL + i1) = make_float2(l0, l1);
    }
}

// ---------------- launch ----------------
extern "C" void kernel_launch(void* const* d_in, const int* in_sizes, int n_in,
                              void* d_out, int out_size)
{
    const float* q  = (const float*)d_in[0];
    const float* k  = (const float*)d_in[1];
    const float* v  = (const float*)d_in[2];
    // d_in[3] is the causal mask -> handled analytically
    const float* Wq = (const float*)d_in[4];
    const float* Wk = (const float*)d_in[5];
    const float* Wv = (const float*)d_in[6];
    const float* Wo = (const float*)d_in[7];
    float* out = (float*)d_out;

    auto ga = [](const void* sym) {
        void* p; cudaGetSymbolAddress(&p, sym); return (float*)p;
    };
    float *qH = ga(g_q_hi), *qL = ga(g_q_lo);
    float *kH = ga(g_k_hi), *kL = ga(g_k_lo);
    float *vH = ga(g_v_hi), *vL = ga(g_v_lo);
    float *WqH = ga(g_Wq_hi), *WqL = ga(g_Wq_lo);
    float *WkH = ga(g_Wk_hi), *WkL = ga(g_Wk_lo);
    float *WvH = ga(g_Wv_hi), *WvL = ga(g_Wv_lo);
    float *WoH = ga(g_Wo_hi), *WoL = ga(g_Wo_lo);
    float *qhH = ga(g_qh_hi), *qhL = ga(g_qh_lo);
    float *khH = ga(g_kh_hi), *khL = ga(g_kh_lo);
    float *vhH = ga(g_vh_hi), *vhL = ga(g_vh_lo);
    float *attH = ga(g_att_hi), *attL = ga(g_att_lo);

    static int smem_set = 0;
    if (!smem_set) {
        cudaFuncSetAttribute(gemm_ps, cudaFuncAttributeMaxDynamicSharedMemorySize, GEMM_SMEM);
        cudaFuncSetAttribute(attn_ps, cudaFuncAttributeMaxDynamicSharedMemorySize, ATTN_SMEM);
        smem_set = 1;
    }

    // 1. batched split pre-pass (q,k,v: 1M float4; weights: 256K float4)
    SplitBatch sb;
    int n4in = MROWS * DM / 4;   // 1048576
    int n4w  = DM * DM / 4;      // 262144
    sb.e[0] = {q,  qH,  qL,  n4in};
    sb.e[1] = {k,  kH,  kL,  n4in};
    sb.e[2] = {v,  vH,  vL,  n4in};
    sb.e[3] = {Wq, WqH, WqL, n4w};
    sb.e[4] = {Wk, WkH, WkL, n4w};
    sb.e[5] = {Wv, WvH, WvL, n4w};
    sb.e[6] = {Wo, WoH, WoL, n4w};
    split7<<<dim3(n4in / 256, 1, 7), 256>>>(sb);

    // 2. three projection GEMMs, one batched launch, split outputs
    GemmBatch gp;
    gp.writeSplit = 1;
    gp.e[0] = {qH, qL, WqH, WqL, qhH, qhL};
    gp.e[1] = {kH, kL, WkH, WkL, khH, khL};
    gp.e[2] = {vH, vL, WvH, WvL, vhH, vhL};
    gemm_ps<<<dim3(DM / GBN, MROWS / GBM, 3), 256, GEMM_SMEM>>>(gp, MROWS, DM, DM);

    // 3. attention (consumes pre-split, produces pre-split att)
    attn_ps<<<dim3(L_ / TQ, B_ * H_), 128, ATTN_SMEM>>>(
        qhH, qhL, khH, khL, vhH, vhL, attH, attL);

    // 4. output GEMM, raw fp32 result
    GemmBatch go;
    go.writeSplit = 0;
    go.e[0] = {attH, attL, WoH, WoL, out, nullptr};
    go.e[1] = go.e[0];
    go.e[2] = go.e[0];
    gemm_ps<<<dim3(DM / GBN, MROWS / GBM, 1), 256, GEMM_SMEM>>>(go, MROWS, DM, DM);
}